// round 8
// baseline (speedup 1.0000x reference)
#include <cuda_runtime.h>
#include <cuda_bf16.h>

// Problem constants
#define BB 8
#define CC 64
#define HP 32
#define WP 32
#define NN 1024          // HP*WP
#define NHEADS 16
// scale * log2(e) = 0.5 * 1.4426950408889634
#define ALPHA 0.72134752044448169f

// Scratch (no cudaMalloc allowed) — float4 for 16B alignment
__device__ float4 g_q4[BB * NHEADS * NN];      // [b][h][n][4], q pre-scaled by ALPHA
__device__ float4 g_k4[BB * NHEADS * NN];
__device__ float4 g_v4[BB * NHEADS * NN];
__device__ float4 g_o4[BB * NN * NHEADS];      // [b][n][h][4] == (B,N,64)
__device__ unsigned char g_idx[BB * CC * NN];  // argmax within 2x2 window

// ---- packed fp32 (f32x2) helpers — FFMA2 only reachable via explicit PTX ----
__device__ __forceinline__ unsigned long long pack2(float a, float b) {
    unsigned long long r;
    asm("mov.b64 %0, {%1,%2};" : "=l"(r) : "f"(a), "f"(b));
    return r;
}
__device__ __forceinline__ void unpack2(unsigned long long p, float& a, float& b) {
    asm("mov.b64 {%0,%1}, %2;" : "=f"(a), "=f"(b) : "l"(p));
}
__device__ __forceinline__ unsigned long long mul2(unsigned long long a, unsigned long long b) {
    unsigned long long r;
    asm("mul.rn.f32x2 %0, %1, %2;" : "=l"(r) : "l"(a), "l"(b));
    return r;
}
__device__ __forceinline__ unsigned long long add2(unsigned long long a, unsigned long long b) {
    unsigned long long r;
    asm("add.rn.f32x2 %0, %1, %2;" : "=l"(r) : "l"(a), "l"(b));
    return r;
}
__device__ __forceinline__ unsigned long long fma2(unsigned long long a, unsigned long long b,
                                                   unsigned long long c) {
    unsigned long long r;
    asm("fma.rn.f32x2 %0, %1, %2, %3;" : "=l"(r) : "l"(a), "l"(b), "l"(c));
    return r;
}
__device__ __forceinline__ float ex2f(float x) {
    float r;
    asm("ex2.approx.f32 %0, %1;" : "=f"(r) : "f"(x));
    return r;
}

// ---------------------------------------------------------------------------
// Kernel A: 2x2 maxpool + argmax, then qkv = t @ w_qkv (64 x 192)
// grid 256 = (b, hp), 256 threads
// ---------------------------------------------------------------------------
__global__ __launch_bounds__(256) void kA(const float* __restrict__ x,
                                          const float* __restrict__ wq) {
    __shared__ float tsm[64 * 32];  // [c][wp]
    const int tid = threadIdx.x;
    const int blk = blockIdx.x;
    const int b = blk >> 5, hp = blk & 31;

    // Phase 1: pooling. pair p -> (c, wp); coalesced float2 loads along w.
#pragma unroll
    for (int s = 0; s < 8; s++) {
        int p = tid + s * 256;
        int c = p >> 5, wp = p & 31;
        const float* base = x + (((b * 64 + c) * 64 + 2 * hp) * 64 + 2 * wp);
        float2 a  = *(const float2*)(base);
        float2 d2 = *(const float2*)(base + 64);
        float best = a.x; int bi = 0;
        if (a.y  > best) { best = a.y;  bi = 1; }
        if (d2.x > best) { best = d2.x; bi = 2; }
        if (d2.y > best) { best = d2.y; bi = 3; }
        tsm[c * 32 + wp] = best;
        g_idx[(b * 64 + c) * 1024 + (hp * 32 + wp)] = (unsigned char)bi;
    }
    __syncthreads();

    // Phase 2: row (wp) x 24 cols per thread; t broadcast from smem, w via L1.
    const int wp = tid >> 3;
    const int col0 = (tid & 7) * 24;
    float acc[24];
#pragma unroll
    for (int j = 0; j < 24; j++) acc[j] = 0.f;

#pragma unroll 4
    for (int c = 0; c < 64; c++) {
        float tv = tsm[c * 32 + wp];
        const float4* wrow = (const float4*)(wq + c * 192 + col0);
#pragma unroll
        for (int j4 = 0; j4 < 6; j4++) {
            float4 wv = wrow[j4];
            acc[j4 * 4 + 0] = fmaf(tv, wv.x, acc[j4 * 4 + 0]);
            acc[j4 * 4 + 1] = fmaf(tv, wv.y, acc[j4 * 4 + 1]);
            acc[j4 * 4 + 2] = fmaf(tv, wv.z, acc[j4 * 4 + 2]);
            acc[j4 * 4 + 3] = fmaf(tv, wv.w, acc[j4 * 4 + 3]);
        }
    }

    const int n = hp * 32 + wp;
    float* gq = (float*)g_q4;
    float* gk = (float*)g_k4;
    float* gv = (float*)g_v4;
#pragma unroll
    for (int j = 0; j < 24; j++) {
        int col = col0 + j;
        int sp = col >> 6, rem = col & 63;
        int hh = rem >> 2, dd = rem & 3;
        int off = ((b * 16 + hh) * 1024 + n) * 4 + dd;
        float v = acc[j];
        if (sp == 0)      gq[off] = v * ALPHA;   // fold scale*log2e into q
        else if (sp == 1) gk[off] = v;
        else              gv[off] = v;
    }
}

// ---------------------------------------------------------------------------
// Kernel B: attention for one (b, h). K/V m-pair-interleaved in smem so each
// LDS.128 yields two f32x2 operands; max-free exp2 softmax; 2 m's per iter
// via packed fma.rn.f32x2. grid 128, 512 threads, 2 queries per thread.
// ---------------------------------------------------------------------------
__global__ __launch_bounds__(512) void kB() {
    // interleaved layout per m-pair mp: A = (kx_e,kx_o,ky_e,ky_o), B = (kz_e,kz_o,kw_e,kw_o)
    __shared__ float4 ksmA[512], ksmB[512];
    __shared__ float4 vsmA[512], vsmB[512];
    const int tid = threadIdx.x;
    const int blk = blockIdx.x;
    const int b = blk >> 4, h = blk & 15;

    const float4* kg = g_k4 + (b * 16 + h) * 1024;
    const float4* vg = g_v4 + (b * 16 + h) * 1024;
    {
        float4 k0 = kg[2 * tid], k1 = kg[2 * tid + 1];
        ksmA[tid] = make_float4(k0.x, k1.x, k0.y, k1.y);
        ksmB[tid] = make_float4(k0.z, k1.z, k0.w, k1.w);
        float4 v0 = vg[2 * tid], v1 = vg[2 * tid + 1];
        vsmA[tid] = make_float4(v0.x, v1.x, v0.y, v1.y);
        vsmB[tid] = make_float4(v0.z, v1.z, v0.w, v1.w);
    }

    const float4* qg = g_q4 + (b * 16 + h) * 1024;
    float4 q0 = qg[tid];
    float4 q1 = qg[tid + 512];
    // broadcast-packed query components (hoisted out of the loop)
    unsigned long long q0x = pack2(q0.x, q0.x), q0y = pack2(q0.y, q0.y);
    unsigned long long q0z = pack2(q0.z, q0.z), q0w = pack2(q0.w, q0.w);
    unsigned long long q1x = pack2(q1.x, q1.x), q1y = pack2(q1.y, q1.y);
    unsigned long long q1z = pack2(q1.z, q1.z), q1w = pack2(q1.w, q1.w);
    __syncthreads();

    unsigned long long s0 = 0ull, ax0 = 0ull, ay0 = 0ull, az0 = 0ull, aw0 = 0ull;
    unsigned long long s1 = 0ull, ax1 = 0ull, ay1 = 0ull, az1 = 0ull, aw1 = 0ull;

#pragma unroll 2
    for (int mp = 0; mp < 512; mp++) {
        // two LDS.128 -> four aligned f32x2 K operands (broadcast, conflict-free)
        ulonglong2 ka = *(const ulonglong2*)&ksmA[mp];  // .x = kx pair, .y = ky pair
        ulonglong2 kb = *(const ulonglong2*)&ksmB[mp];  // .x = kz pair, .y = kw pair

        unsigned long long d0 = mul2(q0x, ka.x);
        d0 = fma2(q0y, ka.y, d0);
        d0 = fma2(q0z, kb.x, d0);
        d0 = fma2(q0w, kb.y, d0);
        unsigned long long d1 = mul2(q1x, ka.x);
        d1 = fma2(q1y, ka.y, d1);
        d1 = fma2(q1z, kb.x, d1);
        d1 = fma2(q1w, kb.y, d1);

        float d0e, d0o, d1e, d1o;
        unpack2(d0, d0e, d0o);
        unpack2(d1, d1e, d1o);
        unsigned long long e0 = pack2(ex2f(d0e), ex2f(d0o));
        unsigned long long e1 = pack2(ex2f(d1e), ex2f(d1o));

        ulonglong2 va = *(const ulonglong2*)&vsmA[mp];
        ulonglong2 vb = *(const ulonglong2*)&vsmB[mp];

        s0  = add2(s0, e0);
        ax0 = fma2(e0, va.x, ax0);
        ay0 = fma2(e0, va.y, ay0);
        az0 = fma2(e0, vb.x, az0);
        aw0 = fma2(e0, vb.y, aw0);
        s1  = add2(s1, e1);
        ax1 = fma2(e1, va.x, ax1);
        ay1 = fma2(e1, va.y, ay1);
        az1 = fma2(e1, vb.x, az1);
        aw1 = fma2(e1, vb.y, aw1);
    }

    float se, so, xe, xo, ye, yo, ze, zo, we, wo;
    unpack2(s0, se, so);
    float r0 = 1.0f / (se + so);
    unpack2(ax0, xe, xo); unpack2(ay0, ye, yo);
    unpack2(az0, ze, zo); unpack2(aw0, we, wo);
    float4 o0 = make_float4((xe + xo) * r0, (ye + yo) * r0, (ze + zo) * r0, (we + wo) * r0);

    unpack2(s1, se, so);
    float r1 = 1.0f / (se + so);
    unpack2(ax1, xe, xo); unpack2(ay1, ye, yo);
    unpack2(az1, ze, zo); unpack2(aw1, we, wo);
    float4 o1 = make_float4((xe + xo) * r1, (ye + yo) * r1, (ze + zo) * r1, (we + wo) * r1);

    g_o4[(b * 1024 + tid) * 16 + h]       = o0;
    g_o4[(b * 1024 + tid + 512) * 16 + h] = o1;
}

// ---------------------------------------------------------------------------
// Kernel C: o @ w_proj (64x64) + BN affine + argmax unpool scatter.
// grid 256 = (b, hp), 256 threads.
// ---------------------------------------------------------------------------
__global__ __launch_bounds__(256) void kC(const float* __restrict__ wproj,
                                          const float* __restrict__ gamma,
                                          const float* __restrict__ beta,
                                          const float* __restrict__ bmean,
                                          const float* __restrict__ bvar,
                                          float* __restrict__ out) {
    __shared__ float wsm[64 * 64];
    __shared__ float osm[32 * 64];   // [wp][c]
    __shared__ float psm[32 * 65];   // [wp][j], padded vs bank conflicts
    __shared__ float invs[64], adds[64];

    const int tid = threadIdx.x;
    const int blk = blockIdx.x;
    const int b = blk >> 5, hp = blk & 31;

#pragma unroll
    for (int s = 0; s < 16; s++) wsm[tid + s * 256] = wproj[tid + s * 256];
    const float* og = (const float*)g_o4 + (b * 1024 + hp * 32) * 64;
#pragma unroll
    for (int s = 0; s < 8; s++) osm[tid + s * 256] = og[tid + s * 256];
    if (tid < 64) {
        float inv = gamma[tid] * rsqrtf(bvar[tid] + 1e-5f);
        invs[tid] = inv;
        adds[tid] = fmaf(-bmean[tid], inv, beta[tid]);
    }
    __syncthreads();

    // proj + affine
#pragma unroll
    for (int s = 0; s < 8; s++) {
        int p = tid + s * 256;
        int wpi = p >> 6, j = p & 63;
        float acc = 0.f;
#pragma unroll 8
        for (int c = 0; c < 64; c++)
            acc = fmaf(osm[wpi * 64 + c], wsm[c * 64 + j], acc);
        psm[wpi * 65 + j] = fmaf(acc, invs[j], adds[j]);
    }
    __syncthreads();

    // scatter into 2x2 windows (zeros at non-argmax positions)
#pragma unroll
    for (int s = 0; s < 8; s++) {
        int p = tid + s * 256;
        int c = p >> 5, wpx = p & 31;
        float val = psm[wpx * 65 + c];
        unsigned char kk = g_idx[(b * 64 + c) * 1024 + hp * 32 + wpx];
        float2 top = make_float2(kk == 0 ? val : 0.f, kk == 1 ? val : 0.f);
        float2 bot = make_float2(kk == 2 ? val : 0.f, kk == 3 ? val : 0.f);
        float* ob = out + (((b * 64 + c) * 64 + 2 * hp) * 64 + 2 * wpx);
        *(float2*)(ob)      = top;
        *(float2*)(ob + 64) = bot;
    }
}

// ---------------------------------------------------------------------------
extern "C" void kernel_launch(void* const* d_in, const int* in_sizes, int n_in,
                              void* d_out, int out_size) {
    const float* x      = (const float*)d_in[0];
    const float* w_qkv  = (const float*)d_in[1];
    const float* w_proj = (const float*)d_in[2];
    const float* gamma  = (const float*)d_in[3];
    const float* beta   = (const float*)d_in[4];
    const float* bmean  = (const float*)d_in[5];
    const float* bvar   = (const float*)d_in[6];
    float* out = (float*)d_out;

    kA<<<256, 256>>>(x, w_qkv);
    kB<<<128, 512>>>();
    kC<<<256, 256>>>(w_proj, gamma, beta, bmean, bvar, out);
}

// round 9
// speedup vs baseline: 1.1244x; 1.1244x over previous
#include <cuda_runtime.h>
#include <cuda_bf16.h>

// Problem constants
#define BB 8
#define CC 64
#define HP 32
#define WP 32
#define NN 1024          // HP*WP
#define NHEADS 16
// scale * log2(e) = 0.5 * 1.4426950408889634
#define ALPHA 0.72134752044448169f

// Scratch (no cudaMalloc allowed) — float4 for 16B alignment
__device__ float4 g_q4[BB * NHEADS * NN];      // [b][h][n][4], q pre-scaled by ALPHA
__device__ float4 g_k4[BB * NHEADS * NN];
__device__ float4 g_v4[BB * NHEADS * NN];
__device__ float4 g_o4[BB * NN * NHEADS];      // [b][n][h][4] == (B,N,64)
__device__ unsigned char g_idx[BB * CC * NN];  // argmax within 2x2 window

// ---- packed fp32 (f32x2) helpers — FFMA2 only reachable via explicit PTX ----
__device__ __forceinline__ unsigned long long pack2(float a, float b) {
    unsigned long long r;
    asm("mov.b64 %0, {%1,%2};" : "=l"(r) : "f"(a), "f"(b));
    return r;
}
__device__ __forceinline__ void unpack2(unsigned long long p, float& a, float& b) {
    asm("mov.b64 {%0,%1}, %2;" : "=f"(a), "=f"(b) : "l"(p));
}
__device__ __forceinline__ unsigned long long mul2(unsigned long long a, unsigned long long b) {
    unsigned long long r;
    asm("mul.rn.f32x2 %0, %1, %2;" : "=l"(r) : "l"(a), "l"(b));
    return r;
}
__device__ __forceinline__ unsigned long long add2(unsigned long long a, unsigned long long b) {
    unsigned long long r;
    asm("add.rn.f32x2 %0, %1, %2;" : "=l"(r) : "l"(a), "l"(b));
    return r;
}
__device__ __forceinline__ unsigned long long fma2(unsigned long long a, unsigned long long b,
                                                   unsigned long long c) {
    unsigned long long r;
    asm("fma.rn.f32x2 %0, %1, %2, %3;" : "=l"(r) : "l"(a), "l"(b), "l"(c));
    return r;
}
__device__ __forceinline__ float ex2f(float x) {
    float r;
    asm("ex2.approx.f32 %0, %1;" : "=f"(r) : "f"(x));
    return r;
}

// ---------------------------------------------------------------------------
// Kernel A: 2x2 maxpool + argmax, then qkv = t @ w_qkv (64 x 192).
// grid 512 = (b, hp, colhalf), 256 threads. Weight half staged in SMEM so
// the inner loop is conflict-free LDS.128 broadcast instead of multi-line
// LDG replays (the R8 ncu bottleneck: L1=67.5%, fma=7.4%).
// ---------------------------------------------------------------------------
__global__ __launch_bounds__(256) void kA(const float* __restrict__ x,
                                          const float* __restrict__ wq) {
    __shared__ float wsm[64 * 96];  // [c][j], this block's 96-col half, 24KB
    __shared__ float tsm[64 * 32];  // [c][wp], 8KB
    const int tid = threadIdx.x;
    const int blk = blockIdx.x;
    const int half = blk & 1;
    const int hp = (blk >> 1) & 31;
    const int b = blk >> 6;

    // Stage weight half: 64 rows x 96 floats = 1536 float4, coalesced.
#pragma unroll
    for (int s = 0; s < 6; s++) {
        int idx = tid + s * 256;             // [0, 1536)
        int c = idx / 24, j4 = idx % 24;     // 24 float4 per row
        float4 wv = *(const float4*)(wq + c * 192 + half * 96 + j4 * 4);
        *(float4*)&wsm[c * 96 + j4 * 4] = wv;
    }

    // Pooling (both halves compute; only half 0 writes g_idx).
#pragma unroll
    for (int s = 0; s < 8; s++) {
        int p = tid + s * 256;
        int c = p >> 5, wp = p & 31;
        const float* base = x + (((b * 64 + c) * 64 + 2 * hp) * 64 + 2 * wp);
        float2 a  = *(const float2*)(base);
        float2 d2 = *(const float2*)(base + 64);
        float best = a.x; int bi = 0;
        if (a.y  > best) { best = a.y;  bi = 1; }
        if (d2.x > best) { best = d2.x; bi = 2; }
        if (d2.y > best) { best = d2.y; bi = 3; }
        tsm[c * 32 + wp] = best;
        if (half == 0)
            g_idx[(b * 64 + c) * 1024 + (hp * 32 + wp)] = (unsigned char)bi;
    }
    __syncthreads();

    // GEMM: thread = (wp, colg); 12 cols per thread, all from SMEM.
    const int wp = tid >> 3;
    const int colg = tid & 7;           // 8 groups x 12 cols = 96
    float acc[12];
#pragma unroll
    for (int j = 0; j < 12; j++) acc[j] = 0.f;

#pragma unroll 4
    for (int c = 0; c < 64; c++) {
        float tv = tsm[c * 32 + wp];
        const float4* wrow = (const float4*)&wsm[c * 96 + colg * 12];  // 48B-aligned
#pragma unroll
        for (int j4 = 0; j4 < 3; j4++) {
            float4 wv = wrow[j4];
            acc[j4 * 4 + 0] = fmaf(tv, wv.x, acc[j4 * 4 + 0]);
            acc[j4 * 4 + 1] = fmaf(tv, wv.y, acc[j4 * 4 + 1]);
            acc[j4 * 4 + 2] = fmaf(tv, wv.z, acc[j4 * 4 + 2]);
            acc[j4 * 4 + 3] = fmaf(tv, wv.w, acc[j4 * 4 + 3]);
        }
    }

    const int n = hp * 32 + wp;
    float* gq = (float*)g_q4;
    float* gk = (float*)g_k4;
    float* gv = (float*)g_v4;
#pragma unroll
    for (int j = 0; j < 12; j++) {
        int col = half * 96 + colg * 12 + j;
        int sp = col >> 6, rem = col & 63;
        int hh = rem >> 2, dd = rem & 3;
        int off = ((b * 16 + hh) * 1024 + n) * 4 + dd;
        float v = acc[j];
        if (sp == 0)      gq[off] = v * ALPHA;   // fold scale*log2e into q
        else if (sp == 1) gk[off] = v;
        else              gv[off] = v;
    }
}

// ---------------------------------------------------------------------------
// Kernel B: attention for one (b, h). K/V m-pair-interleaved in smem so each
// LDS.128 yields two f32x2 operands; max-free exp2 softmax; 2 m's per iter
// via packed fma.rn.f32x2. grid 128, 512 threads, 2 queries per thread.
// ---------------------------------------------------------------------------
__global__ __launch_bounds__(512) void kB() {
    // interleaved layout per m-pair mp: A = (kx_e,kx_o,ky_e,ky_o), B = (kz_e,kz_o,kw_e,kw_o)
    __shared__ float4 ksmA[512], ksmB[512];
    __shared__ float4 vsmA[512], vsmB[512];
    const int tid = threadIdx.x;
    const int blk = blockIdx.x;
    const int b = blk >> 4, h = blk & 15;

    const float4* kg = g_k4 + (b * 16 + h) * 1024;
    const float4* vg = g_v4 + (b * 16 + h) * 1024;
    {
        float4 k0 = kg[2 * tid], k1 = kg[2 * tid + 1];
        ksmA[tid] = make_float4(k0.x, k1.x, k0.y, k1.y);
        ksmB[tid] = make_float4(k0.z, k1.z, k0.w, k1.w);
        float4 v0 = vg[2 * tid], v1 = vg[2 * tid + 1];
        vsmA[tid] = make_float4(v0.x, v1.x, v0.y, v1.y);
        vsmB[tid] = make_float4(v0.z, v1.z, v0.w, v1.w);
    }

    const float4* qg = g_q4 + (b * 16 + h) * 1024;
    float4 q0 = qg[tid];
    float4 q1 = qg[tid + 512];
    // broadcast-packed query components (hoisted out of the loop)
    unsigned long long q0x = pack2(q0.x, q0.x), q0y = pack2(q0.y, q0.y);
    unsigned long long q0z = pack2(q0.z, q0.z), q0w = pack2(q0.w, q0.w);
    unsigned long long q1x = pack2(q1.x, q1.x), q1y = pack2(q1.y, q1.y);
    unsigned long long q1z = pack2(q1.z, q1.z), q1w = pack2(q1.w, q1.w);
    __syncthreads();

    unsigned long long s0 = 0ull, ax0 = 0ull, ay0 = 0ull, az0 = 0ull, aw0 = 0ull;
    unsigned long long s1 = 0ull, ax1 = 0ull, ay1 = 0ull, az1 = 0ull, aw1 = 0ull;

#pragma unroll 2
    for (int mp = 0; mp < 512; mp++) {
        // two LDS.128 -> four aligned f32x2 K operands (broadcast, conflict-free)
        ulonglong2 ka = *(const ulonglong2*)&ksmA[mp];  // .x = kx pair, .y = ky pair
        ulonglong2 kb = *(const ulonglong2*)&ksmB[mp];  // .x = kz pair, .y = kw pair

        unsigned long long d0 = mul2(q0x, ka.x);
        d0 = fma2(q0y, ka.y, d0);
        d0 = fma2(q0z, kb.x, d0);
        d0 = fma2(q0w, kb.y, d0);
        unsigned long long d1 = mul2(q1x, ka.x);
        d1 = fma2(q1y, ka.y, d1);
        d1 = fma2(q1z, kb.x, d1);
        d1 = fma2(q1w, kb.y, d1);

        float d0e, d0o, d1e, d1o;
        unpack2(d0, d0e, d0o);
        unpack2(d1, d1e, d1o);
        unsigned long long e0 = pack2(ex2f(d0e), ex2f(d0o));
        unsigned long long e1 = pack2(ex2f(d1e), ex2f(d1o));

        ulonglong2 va = *(const ulonglong2*)&vsmA[mp];
        ulonglong2 vb = *(const ulonglong2*)&vsmB[mp];

        s0  = add2(s0, e0);
        ax0 = fma2(e0, va.x, ax0);
        ay0 = fma2(e0, va.y, ay0);
        az0 = fma2(e0, vb.x, az0);
        aw0 = fma2(e0, vb.y, aw0);
        s1  = add2(s1, e1);
        ax1 = fma2(e1, va.x, ax1);
        ay1 = fma2(e1, va.y, ay1);
        az1 = fma2(e1, vb.x, az1);
        aw1 = fma2(e1, vb.y, aw1);
    }

    float se, so, xe, xo, ye, yo, ze, zo, we, wo;
    unpack2(s0, se, so);
    float r0 = 1.0f / (se + so);
    unpack2(ax0, xe, xo); unpack2(ay0, ye, yo);
    unpack2(az0, ze, zo); unpack2(aw0, we, wo);
    float4 o0 = make_float4((xe + xo) * r0, (ye + yo) * r0, (ze + zo) * r0, (we + wo) * r0);

    unpack2(s1, se, so);
    float r1 = 1.0f / (se + so);
    unpack2(ax1, xe, xo); unpack2(ay1, ye, yo);
    unpack2(az1, ze, zo); unpack2(aw1, we, wo);
    float4 o1 = make_float4((xe + xo) * r1, (ye + yo) * r1, (ze + zo) * r1, (we + wo) * r1);

    g_o4[(b * 1024 + tid) * 16 + h]       = o0;
    g_o4[(b * 1024 + tid + 512) * 16 + h] = o1;
}

// ---------------------------------------------------------------------------
// Kernel C: o @ w_proj (64x64) + BN affine + argmax unpool scatter.
// grid 256 = (b, hp), 256 threads. Register-tiled: 8 outputs/thread so the
// inner loop is 3 LDS + 8 FFMA per c (was 16 LDS + 8 FFMA).
// ---------------------------------------------------------------------------
__global__ __launch_bounds__(256) void kC(const float* __restrict__ wproj,
                                          const float* __restrict__ gamma,
                                          const float* __restrict__ beta,
                                          const float* __restrict__ bmean,
                                          const float* __restrict__ bvar,
                                          float* __restrict__ out) {
    __shared__ float wsm[64 * 64];
    __shared__ float osm[32 * 64];   // [wp][c]
    __shared__ float psm[32 * 65];   // [wp][j], padded vs bank conflicts
    __shared__ float invs[64], adds[64];

    const int tid = threadIdx.x;
    const int blk = blockIdx.x;
    const int b = blk >> 5, hp = blk & 31;

#pragma unroll
    for (int s = 0; s < 16; s++) wsm[tid + s * 256] = wproj[tid + s * 256];
    const float* og = (const float*)g_o4 + (b * 1024 + hp * 32) * 64;
#pragma unroll
    for (int s = 0; s < 8; s++) osm[tid + s * 256] = og[tid + s * 256];
    if (tid < 64) {
        float inv = gamma[tid] * rsqrtf(bvar[tid] + 1e-5f);
        invs[tid] = inv;
        adds[tid] = fmaf(-bmean[tid], inv, beta[tid]);
    }
    __syncthreads();

    // proj + affine: thread = (wp, colg); 8 cols per thread in registers.
    {
        const int wp = tid >> 3;
        const int colg = tid & 7;
        float acc[8];
#pragma unroll
        for (int j = 0; j < 8; j++) acc[j] = 0.f;
#pragma unroll 4
        for (int c = 0; c < 64; c++) {
            float ov = osm[wp * 64 + c];
            const float4* wrow = (const float4*)&wsm[c * 64 + colg * 8];
            float4 w0 = wrow[0], w1 = wrow[1];
            acc[0] = fmaf(ov, w0.x, acc[0]);
            acc[1] = fmaf(ov, w0.y, acc[1]);
            acc[2] = fmaf(ov, w0.z, acc[2]);
            acc[3] = fmaf(ov, w0.w, acc[3]);
            acc[4] = fmaf(ov, w1.x, acc[4]);
            acc[5] = fmaf(ov, w1.y, acc[5]);
            acc[6] = fmaf(ov, w1.z, acc[6]);
            acc[7] = fmaf(ov, w1.w, acc[7]);
        }
#pragma unroll
        for (int j = 0; j < 8; j++) {
            int col = colg * 8 + j;
            psm[wp * 65 + col] = fmaf(acc[j], invs[col], adds[col]);
        }
    }
    __syncthreads();

    // scatter into 2x2 windows (zeros at non-argmax positions)
#pragma unroll
    for (int s = 0; s < 8; s++) {
        int p = tid + s * 256;
        int c = p >> 5, wpx = p & 31;
        float val = psm[wpx * 65 + c];
        unsigned char kk = g_idx[(b * 64 + c) * 1024 + hp * 32 + wpx];
        float2 top = make_float2(kk == 0 ? val : 0.f, kk == 1 ? val : 0.f);
        float2 bot = make_float2(kk == 2 ? val : 0.f, kk == 3 ? val : 0.f);
        float* ob = out + (((b * 64 + c) * 64 + 2 * hp) * 64 + 2 * wpx);
        *(float2*)(ob)      = top;
        *(float2*)(ob + 64) = bot;
    }
}

// ---------------------------------------------------------------------------
extern "C" void kernel_launch(void* const* d_in, const int* in_sizes, int n_in,
                              void* d_out, int out_size) {
    const float* x      = (const float*)d_in[0];
    const float* w_qkv  = (const float*)d_in[1];
    const float* w_proj = (const float*)d_in[2];
    const float* gamma  = (const float*)d_in[3];
    const float* beta   = (const float*)d_in[4];
    const float* bmean  = (const float*)d_in[5];
    const float* bvar   = (const float*)d_in[6];
    float* out = (float*)d_out;

    kA<<<512, 256>>>(x, w_qkv);
    kB<<<128, 512>>>();
    kC<<<256, 256>>>(w_proj, gamma, beta, bmean, bvar, out);
}

// round 10
// speedup vs baseline: 1.1451x; 1.0184x over previous
#include <cuda_runtime.h>
#include <cuda_bf16.h>

// Problem constants
#define BB 8
#define CC 64
#define HP 32
#define WP 32
#define NN 1024          // HP*WP
#define NHEADS 16
// scale * log2(e) = 0.5 * 1.4426950408889634
#define ALPHA 0.72134752044448169f

// Scratch (no cudaMalloc allowed) — float4 for 16B alignment
__device__ float4 g_q4[BB * NHEADS * NN];      // [b][h][n][4], q pre-scaled by ALPHA
__device__ float4 g_k4[BB * NHEADS * NN];
__device__ float4 g_v4[BB * NHEADS * NN];
__device__ float4 g_o4[BB * NN * NHEADS];      // [b][n][h][4] == (B,N,64)
__device__ unsigned char g_idx[BB * CC * NN];  // argmax within 2x2 window

// ---- packed fp32 (f32x2) helpers ----
__device__ __forceinline__ unsigned long long pack2(float a, float b) {
    unsigned long long r;
    asm("mov.b64 %0, {%1,%2};" : "=l"(r) : "f"(a), "f"(b));
    return r;
}
__device__ __forceinline__ void unpack2(unsigned long long p, float& a, float& b) {
    asm("mov.b64 {%0,%1}, %2;" : "=f"(a), "=f"(b) : "l"(p));
}
__device__ __forceinline__ unsigned long long mul2(unsigned long long a, unsigned long long b) {
    unsigned long long r;
    asm("mul.rn.f32x2 %0, %1, %2;" : "=l"(r) : "l"(a), "l"(b));
    return r;
}
__device__ __forceinline__ unsigned long long add2(unsigned long long a, unsigned long long b) {
    unsigned long long r;
    asm("add.rn.f32x2 %0, %1, %2;" : "=l"(r) : "l"(a), "l"(b));
    return r;
}
__device__ __forceinline__ unsigned long long fma2(unsigned long long a, unsigned long long b,
                                                   unsigned long long c) {
    unsigned long long r;
    asm("fma.rn.f32x2 %0, %1, %2, %3;" : "=l"(r) : "l"(a), "l"(b), "l"(c));
    return r;
}
__device__ __forceinline__ float ex2f(float x) {
    float r;
    asm("ex2.approx.f32 %0, %1;" : "=f"(r) : "f"(x));
    return r;
}

// ---------------------------------------------------------------------------
// Kernel A: 2x2 maxpool + argmax, then qkv = t @ w_qkv (64 x 192).
// grid 256 = (b, hp-pair, colhalf), 256 threads. Each block: 64 n x 96 cols.
// Thread computes 2 n x 12 cols (24 acc) -> weight LDS amortized 2x vs R9,
// epilogue stores 3 float4 per n instead of 12 scalar STG.
// ---------------------------------------------------------------------------
__global__ __launch_bounds__(256) void kA(const float* __restrict__ x,
                                          const float* __restrict__ wq) {
    __shared__ float wsm[64 * 96];  // [c][j], 24KB
    __shared__ float tsm[64 * 64];  // [c][n_local], 16KB
    const int tid = threadIdx.x;
    const int blk = blockIdx.x;
    const int half = blk & 1;
    const int hpg = (blk >> 1) & 15;   // pair of hp rows: hp = hpg*2 + hl
    const int b = blk >> 5;

    // Stage weight half: 64 rows x 96 floats = 1536 float4, coalesced.
#pragma unroll
    for (int s = 0; s < 6; s++) {
        int idx = tid + s * 256;             // [0, 1536)
        int c = idx / 24, j4 = idx % 24;
        *(float4*)&wsm[c * 96 + j4 * 4] =
            *(const float4*)(wq + c * 192 + half * 96 + j4 * 4);
    }

    // Pooling: 64 c x 2 hp x 32 wp = 4096 units, 16 per thread.
#pragma unroll
    for (int s = 0; s < 16; s++) {
        int p = tid + s * 256;
        int c = p >> 6, r = p & 63;
        int hl = r >> 5, wp = r & 31;
        int hp = hpg * 2 + hl;
        const float* base = x + (((b * 64 + c) * 64 + 2 * hp) * 64 + 2 * wp);
        float2 a  = *(const float2*)(base);
        float2 d2 = *(const float2*)(base + 64);
        float best = a.x; int bi = 0;
        if (a.y  > best) { best = a.y;  bi = 1; }
        if (d2.x > best) { best = d2.x; bi = 2; }
        if (d2.y > best) { best = d2.y; bi = 3; }
        tsm[c * 64 + hl * 32 + wp] = best;
        if (half == 0)
            g_idx[(b * 64 + c) * 1024 + hp * 32 + wp] = (unsigned char)bi;
    }
    __syncthreads();

    // GEMM: thread = (ng, colg); 2 n x 12 cols in registers, all from SMEM.
    const int ng = tid >> 3;            // 32 groups x 2 n = 64 n
    const int colg = tid & 7;           // 8 groups x 12 cols = 96
    float acc0[12], acc1[12];
#pragma unroll
    for (int j = 0; j < 12; j++) { acc0[j] = 0.f; acc1[j] = 0.f; }

#pragma unroll 4
    for (int c = 0; c < 64; c++) {
        float2 tv = *(const float2*)&tsm[c * 64 + ng * 2];
        const float4* wrow = (const float4*)&wsm[c * 96 + colg * 12];
#pragma unroll
        for (int j4 = 0; j4 < 3; j4++) {
            float4 wv = wrow[j4];
            acc0[j4 * 4 + 0] = fmaf(tv.x, wv.x, acc0[j4 * 4 + 0]);
            acc0[j4 * 4 + 1] = fmaf(tv.x, wv.y, acc0[j4 * 4 + 1]);
            acc0[j4 * 4 + 2] = fmaf(tv.x, wv.z, acc0[j4 * 4 + 2]);
            acc0[j4 * 4 + 3] = fmaf(tv.x, wv.w, acc0[j4 * 4 + 3]);
            acc1[j4 * 4 + 0] = fmaf(tv.y, wv.x, acc1[j4 * 4 + 0]);
            acc1[j4 * 4 + 1] = fmaf(tv.y, wv.y, acc1[j4 * 4 + 1]);
            acc1[j4 * 4 + 2] = fmaf(tv.y, wv.z, acc1[j4 * 4 + 2]);
            acc1[j4 * 4 + 3] = fmaf(tv.y, wv.w, acc1[j4 * 4 + 3]);
        }
    }

    // Epilogue: 3 float4 stores per n (each 4-col group = one head's 4 dims).
    const int nbase = hpg * 64 + ng * 2;
#pragma unroll
    for (int g = 0; g < 3; g++) {
        int col = half * 96 + colg * 12 + g * 4;   // multiple of 4
        int sp = col >> 6;
        int hh = (col & 63) >> 2;
        float4 v0 = make_float4(acc0[g * 4], acc0[g * 4 + 1], acc0[g * 4 + 2], acc0[g * 4 + 3]);
        float4 v1 = make_float4(acc1[g * 4], acc1[g * 4 + 1], acc1[g * 4 + 2], acc1[g * 4 + 3]);
        int off = (b * 16 + hh) * 1024 + nbase;
        if (sp == 0) {
            v0.x *= ALPHA; v0.y *= ALPHA; v0.z *= ALPHA; v0.w *= ALPHA;
            v1.x *= ALPHA; v1.y *= ALPHA; v1.z *= ALPHA; v1.w *= ALPHA;
            g_q4[off] = v0; g_q4[off + 1] = v1;
        } else if (sp == 1) {
            g_k4[off] = v0; g_k4[off + 1] = v1;
        } else {
            g_v4[off] = v0; g_v4[off + 1] = v1;
        }
    }
}

// ---------------------------------------------------------------------------
// Kernel B: attention. grid 256 = (b, h, query-half), 512 threads, 1 query
// per thread. K/V m-pair-interleaved in smem so each LDS.128 yields two f32x2
// operands; max-free exp2 softmax; 2 m's per iter via packed fma.rn.f32x2.
// 2 blocks/SM across all 148 SMs (was 1 block on 128 SMs).
// ---------------------------------------------------------------------------
__global__ __launch_bounds__(512) void kB() {
    __shared__ float4 ksmA[512], ksmB[512];
    __shared__ float4 vsmA[512], vsmB[512];
    const int tid = threadIdx.x;
    const int blk = blockIdx.x;
    const int b = blk >> 5, h = (blk >> 1) & 15, qh = blk & 1;

    const float4* kg = g_k4 + (b * 16 + h) * 1024;
    const float4* vg = g_v4 + (b * 16 + h) * 1024;
    {
        float4 k0 = kg[2 * tid], k1 = kg[2 * tid + 1];
        ksmA[tid] = make_float4(k0.x, k1.x, k0.y, k1.y);
        ksmB[tid] = make_float4(k0.z, k1.z, k0.w, k1.w);
        float4 v0 = vg[2 * tid], v1 = vg[2 * tid + 1];
        vsmA[tid] = make_float4(v0.x, v1.x, v0.y, v1.y);
        vsmB[tid] = make_float4(v0.z, v1.z, v0.w, v1.w);
    }

    const int nq = qh * 512 + tid;
    float4 q0 = ((const float4*)g_q4)[(b * 16 + h) * 1024 + nq];
    unsigned long long qx = pack2(q0.x, q0.x), qy = pack2(q0.y, q0.y);
    unsigned long long qz = pack2(q0.z, q0.z), qw = pack2(q0.w, q0.w);
    __syncthreads();

    unsigned long long s0 = 0ull, ax0 = 0ull, ay0 = 0ull, az0 = 0ull, aw0 = 0ull;

#pragma unroll 4
    for (int mp = 0; mp < 512; mp++) {
        ulonglong2 ka = *(const ulonglong2*)&ksmA[mp];  // kx pair, ky pair
        ulonglong2 kb = *(const ulonglong2*)&ksmB[mp];  // kz pair, kw pair

        unsigned long long d0 = mul2(qx, ka.x);
        d0 = fma2(qy, ka.y, d0);
        d0 = fma2(qz, kb.x, d0);
        d0 = fma2(qw, kb.y, d0);

        float d0e, d0o;
        unpack2(d0, d0e, d0o);
        unsigned long long e0 = pack2(ex2f(d0e), ex2f(d0o));

        ulonglong2 va = *(const ulonglong2*)&vsmA[mp];
        ulonglong2 vb = *(const ulonglong2*)&vsmB[mp];

        s0  = add2(s0, e0);
        ax0 = fma2(e0, va.x, ax0);
        ay0 = fma2(e0, va.y, ay0);
        az0 = fma2(e0, vb.x, az0);
        aw0 = fma2(e0, vb.y, aw0);
    }

    float se, so, xe, xo, ye, yo, ze, zo, we, wo;
    unpack2(s0, se, so);
    float r0 = 1.0f / (se + so);
    unpack2(ax0, xe, xo); unpack2(ay0, ye, yo);
    unpack2(az0, ze, zo); unpack2(aw0, we, wo);
    float4 o0 = make_float4((xe + xo) * r0, (ye + yo) * r0, (ze + zo) * r0, (we + wo) * r0);

    g_o4[(b * 1024 + nq) * 16 + h] = o0;
}

// ---------------------------------------------------------------------------
// Kernel C: o @ w_proj (64x64) + BN affine + argmax unpool scatter.
// grid 256 = (b, hp), 256 threads, register-tiled 8 outputs/thread.
// ---------------------------------------------------------------------------
__global__ __launch_bounds__(256) void kC(const float* __restrict__ wproj,
                                          const float* __restrict__ gamma,
                                          const float* __restrict__ beta,
                                          const float* __restrict__ bmean,
                                          const float* __restrict__ bvar,
                                          float* __restrict__ out) {
    __shared__ float wsm[64 * 64];
    __shared__ float osm[32 * 64];   // [wp][c]
    __shared__ float psm[32 * 65];   // [wp][j], padded vs bank conflicts
    __shared__ float invs[64], adds[64];

    const int tid = threadIdx.x;
    const int blk = blockIdx.x;
    const int b = blk >> 5, hp = blk & 31;

#pragma unroll
    for (int s = 0; s < 16; s++) wsm[tid + s * 256] = wproj[tid + s * 256];
    const float* og = (const float*)g_o4 + (b * 1024 + hp * 32) * 64;
#pragma unroll
    for (int s = 0; s < 8; s++) osm[tid + s * 256] = og[tid + s * 256];
    if (tid < 64) {
        float inv = gamma[tid] * rsqrtf(bvar[tid] + 1e-5f);
        invs[tid] = inv;
        adds[tid] = fmaf(-bmean[tid], inv, beta[tid]);
    }
    __syncthreads();

    // proj + affine: thread = (wp, colg); 8 cols per thread in registers.
    {
        const int wp = tid >> 3;
        const int colg = tid & 7;
        float acc[8];
#pragma unroll
        for (int j = 0; j < 8; j++) acc[j] = 0.f;
#pragma unroll 4
        for (int c = 0; c < 64; c++) {
            float ov = osm[wp * 64 + c];
            const float4* wrow = (const float4*)&wsm[c * 64 + colg * 8];
            float4 w0 = wrow[0], w1 = wrow[1];
            acc[0] = fmaf(ov, w0.x, acc[0]);
            acc[1] = fmaf(ov, w0.y, acc[1]);
            acc[2] = fmaf(ov, w0.z, acc[2]);
            acc[3] = fmaf(ov, w0.w, acc[3]);
            acc[4] = fmaf(ov, w1.x, acc[4]);
            acc[5] = fmaf(ov, w1.y, acc[5]);
            acc[6] = fmaf(ov, w1.z, acc[6]);
            acc[7] = fmaf(ov, w1.w, acc[7]);
        }
#pragma unroll
        for (int j = 0; j < 8; j++) {
            int col = colg * 8 + j;
            psm[wp * 65 + col] = fmaf(acc[j], invs[col], adds[col]);
        }
    }
    __syncthreads();

    // scatter into 2x2 windows (zeros at non-argmax positions)
#pragma unroll
    for (int s = 0; s < 8; s++) {
        int p = tid + s * 256;
        int c = p >> 5, wpx = p & 31;
        float val = psm[wpx * 65 + c];
        unsigned char kk = g_idx[(b * 64 + c) * 1024 + hp * 32 + wpx];
        float2 top = make_float2(kk == 0 ? val : 0.f, kk == 1 ? val : 0.f);
        float2 bot = make_float2(kk == 2 ? val : 0.f, kk == 3 ? val : 0.f);
        float* ob = out + (((b * 64 + c) * 64 + 2 * hp) * 64 + 2 * wpx);
        *(float2*)(ob)      = top;
        *(float2*)(ob + 64) = bot;
    }
}

// ---------------------------------------------------------------------------
extern "C" void kernel_launch(void* const* d_in, const int* in_sizes, int n_in,
                              void* d_out, int out_size) {
    const float* x      = (const float*)d_in[0];
    const float* w_qkv  = (const float*)d_in[1];
    const float* w_proj = (const float*)d_in[2];
    const float* gamma  = (const float*)d_in[3];
    const float* beta   = (const float*)d_in[4];
    const float* bmean  = (const float*)d_in[5];
    const float* bvar   = (const float*)d_in[6];
    float* out = (float*)d_out;

    kA<<<256, 256>>>(x, w_qkv);
    kB<<<256, 512>>>();
    kC<<<256, 256>>>(w_proj, gamma, beta, bmean, bvar, out);
}